// round 1
// baseline (speedup 1.0000x reference)
#include <cuda_runtime.h>
#include <cstddef>
#include <cstdint>

// ---------------- problem constants ----------------
#define BATCH   2
#define SEQ     1024
#define DMODEL  1024
#define DINNER  2048
#define DTRANK  64
#define DSTATE  16
#define DCONV   4
#define ROWS    (BATCH*SEQ)          // 2048
#define XDBL_W  (DTRANK + 2*DSTATE)  // 96

// ---------------- scratch (device globals; no allocs allowed) ----------------
__device__ float g_xn  [ROWS*DMODEL];        // 8 MB
__device__ float g_xz  [ROWS*2*DINNER];      // 32 MB
__device__ float g_xc  [ROWS*DINNER];        // 16 MB
__device__ float g_xdbl[ROWS*XDBL_W];        // 0.75 MB
__device__ float g_part[8*ROWS*XDBL_W];      // 6 MB
__device__ float g_dt  [ROWS*DINNER];        // 16 MB
__device__ float g_y   [ROWS*DINNER];        // 16 MB

// ---------------- LayerNorm ----------------
__global__ __launch_bounds__(256) void ln_kernel(
    const float* __restrict__ x, const float* __restrict__ g,
    const float* __restrict__ b, float* __restrict__ xn)
{
    int row = blockIdx.x;
    int t = threadIdx.x;
    const float4* xr = (const float4*)(x + (size_t)row*DMODEL);
    float4 v = xr[t];
    float s  = v.x + v.y + v.z + v.w;
    float s2 = v.x*v.x + v.y*v.y + v.z*v.z + v.w*v.w;
    #pragma unroll
    for (int o = 16; o; o >>= 1) {
        s  += __shfl_xor_sync(0xffffffffu, s,  o);
        s2 += __shfl_xor_sync(0xffffffffu, s2, o);
    }
    __shared__ float sh[2][8];
    int w = t >> 5;
    if ((t & 31) == 0) { sh[0][w] = s; sh[1][w] = s2; }
    __syncthreads();
    float S = 0.f, S2 = 0.f;
    #pragma unroll
    for (int i = 0; i < 8; i++) { S += sh[0][i]; S2 += sh[1][i]; }
    float mu  = S * (1.f/DMODEL);
    float var = S2 * (1.f/DMODEL) - mu*mu;
    float inv = rsqrtf(var + 1e-5f);
    float4 gv = ((const float4*)g)[t];
    float4 bv = ((const float4*)b)[t];
    float4 o;
    o.x = (v.x - mu)*inv*gv.x + bv.x;
    o.y = (v.y - mu)*inv*gv.y + bv.y;
    o.z = (v.z - mu)*inv*gv.z + bv.z;
    o.w = (v.w - mu)*inv*gv.w + bv.w;
    ((float4*)(xn + (size_t)row*DMODEL))[t] = o;
}

// ---------------- generic NT SGEMM: C[M,N] = A[M,K] * B[N,K]^T (+bias, epilogue) ----------------
// MODE 0: +bias ; MODE 1: softplus(+bias) ; MODE 2: +bias + residual R[M,N]
__device__ __forceinline__ float softplus_f(float x) {
    return fmaxf(x, 0.f) + log1pf(__expf(-fabsf(x)));
}

template<int MODE>
__global__ __launch_bounds__(256) void sgemm_nt(
    const float* __restrict__ A, int lda,
    const float* __restrict__ B, int ldb,
    const float* __restrict__ bias,
    const float* __restrict__ R,
    float* __restrict__ C,
    int M, int N, int K)
{
    __shared__ float As[8][128];
    __shared__ float Bs[8][128];
    const int bm = blockIdx.y * 128;
    const int bn = blockIdx.x * 128;
    const int tid = threadIdx.x;
    const int lr = tid >> 1;          // 0..127
    const int lc = (tid & 1) * 4;     // 0 or 4
    const int tx = tid & 15;
    const int ty = tid >> 4;

    float acc[8][8];
    #pragma unroll
    for (int i = 0; i < 8; i++)
        #pragma unroll
        for (int j = 0; j < 8; j++) acc[i][j] = 0.f;

    const bool aval = (bm + lr) < M;
    const bool bval = (bn + lr) < N;
    const float* Ap = A + (size_t)(bm + lr)*lda + lc;
    const float* Bp = B + (size_t)(bn + lr)*ldb + lc;

    for (int k0 = 0; k0 < K; k0 += 8) {
        float4 av = aval ? *(const float4*)Ap : make_float4(0,0,0,0);
        float4 bv = bval ? *(const float4*)Bp : make_float4(0,0,0,0);
        Ap += 8; Bp += 8;
        As[lc+0][lr]=av.x; As[lc+1][lr]=av.y; As[lc+2][lr]=av.z; As[lc+3][lr]=av.w;
        Bs[lc+0][lr]=bv.x; Bs[lc+1][lr]=bv.y; Bs[lc+2][lr]=bv.z; Bs[lc+3][lr]=bv.w;
        __syncthreads();
        #pragma unroll
        for (int kk = 0; kk < 8; kk++) {
            float a[8], b[8];
            float4 a0 = *(const float4*)&As[kk][ty*4];
            float4 a1 = *(const float4*)&As[kk][64 + ty*4];
            float4 b0 = *(const float4*)&Bs[kk][tx*4];
            float4 b1 = *(const float4*)&Bs[kk][64 + tx*4];
            a[0]=a0.x;a[1]=a0.y;a[2]=a0.z;a[3]=a0.w;a[4]=a1.x;a[5]=a1.y;a[6]=a1.z;a[7]=a1.w;
            b[0]=b0.x;b[1]=b0.y;b[2]=b0.z;b[3]=b0.w;b[4]=b1.x;b[5]=b1.y;b[6]=b1.z;b[7]=b1.w;
            #pragma unroll
            for (int i = 0; i < 8; i++)
                #pragma unroll
                for (int j = 0; j < 8; j++)
                    acc[i][j] = fmaf(a[i], b[j], acc[i][j]);
        }
        __syncthreads();
    }

    #pragma unroll
    for (int i = 0; i < 8; i++) {
        int m = bm + (i < 4 ? ty*4 + i : 64 + ty*4 + (i-4));
        if (m >= M) continue;
        #pragma unroll
        for (int j = 0; j < 8; j++) {
            int n = bn + (j < 4 ? tx*4 + j : 64 + tx*4 + (j-4));
            if (n >= N) continue;
            float v = acc[i][j] + bias[n];
            if (MODE == 1) v = softplus_f(v);
            if (MODE == 2) v += R[(size_t)m*N + n];
            C[(size_t)m*N + n] = v;
        }
    }
}

// ---------------- depthwise causal conv (K=4) + SiLU ----------------
__global__ __launch_bounds__(256) void conv_silu_kernel(
    const float* __restrict__ xz, const float* __restrict__ cw,
    const float* __restrict__ cb, float* __restrict__ xc)
{
    int idx = blockIdx.x * 256 + threadIdx.x;   // over ROWS*DINNER
    int d = idx & (DINNER - 1);
    int l = (idx >> 11) & (SEQ - 1);
    const float* base = xz + (size_t)(idx >> 11) * (2*DINNER) + d;
    float4 wv = ((const float4*)cw)[d];
    float x0 = (l >= 3) ? base[-3*2*DINNER] : 0.f;
    float x1 = (l >= 2) ? base[-2*2*DINNER] : 0.f;
    float x2 = (l >= 1) ? base[-1*2*DINNER] : 0.f;
    float x3 = base[0];
    float acc = cb[d];
    acc = fmaf(x0, wv.x, acc);
    acc = fmaf(x1, wv.y, acc);
    acc = fmaf(x2, wv.z, acc);
    acc = fmaf(x3, wv.w, acc);
    float sig = 1.f / (1.f + __expf(-acc));
    xc[idx] = acc * sig;
}

// ---------------- skinny GEMM for x_dbl: [2048,96] = xc[2048,2048] * Wx[96,2048]^T (split-K) --------
__global__ __launch_bounds__(256) void gemm_xdbl_part(
    const float* __restrict__ xc, const float* __restrict__ Wx,
    float* __restrict__ part)
{
    const int KC = DINNER / 8;  // 256 per chunk
    __shared__ float As[32][33];
    __shared__ float Bs[32][97];
    int bm = blockIdx.x * 32;
    int kbase = blockIdx.y * KC;
    int t = threadIdx.x;
    int ty = t >> 5;   // 0..7  -> rows ty*4..+3
    int tx = t & 31;   // 0..31 -> cols tx*3..+2
    float acc[4][3];
    #pragma unroll
    for (int i = 0; i < 4; i++)
        #pragma unroll
        for (int j = 0; j < 3; j++) acc[i][j] = 0.f;

    for (int k0 = 0; k0 < KC; k0 += 32) {
        {
            int m = t >> 3, k4 = (t & 7) * 4;
            float4 v = *(const float4*)(xc + (size_t)(bm + m)*DINNER + kbase + k0 + k4);
            As[k4+0][m]=v.x; As[k4+1][m]=v.y; As[k4+2][m]=v.z; As[k4+3][m]=v.w;
        }
        #pragma unroll
        for (int r = 0; r < 3; r++) {
            int i = t + r*256;            // 0..767
            int e = i >> 3, k4 = (i & 7) * 4;
            float4 v = *(const float4*)(Wx + (size_t)e*DINNER + kbase + k0 + k4);
            Bs[k4+0][e]=v.x; Bs[k4+1][e]=v.y; Bs[k4+2][e]=v.z; Bs[k4+3][e]=v.w;
        }
        __syncthreads();
        #pragma unroll
        for (int kk = 0; kk < 32; kk++) {
            float a0=As[kk][ty*4+0], a1=As[kk][ty*4+1], a2=As[kk][ty*4+2], a3=As[kk][ty*4+3];
            float b0=Bs[kk][tx*3+0], b1=Bs[kk][tx*3+1], b2=Bs[kk][tx*3+2];
            acc[0][0]=fmaf(a0,b0,acc[0][0]); acc[0][1]=fmaf(a0,b1,acc[0][1]); acc[0][2]=fmaf(a0,b2,acc[0][2]);
            acc[1][0]=fmaf(a1,b0,acc[1][0]); acc[1][1]=fmaf(a1,b1,acc[1][1]); acc[1][2]=fmaf(a1,b2,acc[1][2]);
            acc[2][0]=fmaf(a2,b0,acc[2][0]); acc[2][1]=fmaf(a2,b1,acc[2][1]); acc[2][2]=fmaf(a2,b2,acc[2][2]);
            acc[3][0]=fmaf(a3,b0,acc[3][0]); acc[3][1]=fmaf(a3,b1,acc[3][1]); acc[3][2]=fmaf(a3,b2,acc[3][2]);
        }
        __syncthreads();
    }
    #pragma unroll
    for (int i = 0; i < 4; i++)
        #pragma unroll
        for (int j = 0; j < 3; j++)
            part[((size_t)blockIdx.y*ROWS + bm + ty*4 + i)*XDBL_W + tx*3 + j] = acc[i][j];
}

__global__ __launch_bounds__(256) void xdbl_reduce(
    const float* __restrict__ part, float* __restrict__ out)
{
    int i = blockIdx.x * 256 + threadIdx.x;   // over ROWS*XDBL_W = 196608
    float s = 0.f;
    #pragma unroll
    for (int c = 0; c < 8; c++) s += part[(size_t)c*ROWS*XDBL_W + i];
    out[i] = s;
}

// ---------------- selective scan (+D skip, +silu(z) gate) ----------------
__global__ __launch_bounds__(32) void scan_kernel(
    const float* __restrict__ xz, const float* __restrict__ xc,
    const float* __restrict__ xdbl, const float* __restrict__ dt,
    const float* __restrict__ A_log, const float* __restrict__ Dp,
    float* __restrict__ y)
{
    int d = blockIdx.x * 32 + threadIdx.x;
    int b = blockIdx.y;

    float Ar[16], h[16];
    #pragma unroll
    for (int s = 0; s < 16; s++) { Ar[s] = -expf(A_log[(size_t)d*16 + s]); h[s] = 0.f; }
    float Dd = Dp[d];

    const float* dtp = dt   + (size_t)b*SEQ*DINNER + d;
    const float* xcp = xc   + (size_t)b*SEQ*DINNER + d;
    const float* zp  = xz   + (size_t)b*SEQ*(2*DINNER) + DINNER + d;
    const float* bcp = xdbl + (size_t)b*SEQ*XDBL_W + DTRANK;
    float*       yp  = y    + (size_t)b*SEQ*DINNER + d;

    // software pipeline: current values + prefetch next
    float dtv = dtp[0], xcv = xcp[0], zv = zp[0];
    float4 B0 = *(const float4*)(bcp+0),  B1 = *(const float4*)(bcp+4);
    float4 B2 = *(const float4*)(bcp+8),  B3 = *(const float4*)(bcp+12);
    float4 C0 = *(const float4*)(bcp+16), C1 = *(const float4*)(bcp+20);
    float4 C2 = *(const float4*)(bcp+24), C3 = *(const float4*)(bcp+28);

    for (int l = 0; l < SEQ; l++) {
        int ln = (l + 1 < SEQ) ? l + 1 : l;
        float ndt = dtp[(size_t)ln*DINNER];
        float nxc = xcp[(size_t)ln*DINNER];
        float nzv = zp [(size_t)ln*(2*DINNER)];
        const float* nb = bcp + (size_t)ln*XDBL_W;
        float4 nB0 = *(const float4*)(nb+0),  nB1 = *(const float4*)(nb+4);
        float4 nB2 = *(const float4*)(nb+8),  nB3 = *(const float4*)(nb+12);
        float4 nC0 = *(const float4*)(nb+16), nC1 = *(const float4*)(nb+20);
        float4 nC2 = *(const float4*)(nb+24), nC3 = *(const float4*)(nb+28);

        float Bv[16], Cv[16];
        *(float4*)&Bv[0]=B0; *(float4*)&Bv[4]=B1; *(float4*)&Bv[8]=B2; *(float4*)&Bv[12]=B3;
        *(float4*)&Cv[0]=C0; *(float4*)&Cv[4]=C1; *(float4*)&Cv[8]=C2; *(float4*)&Cv[12]=C3;

        float dtx = dtv * xcv;
        float y0 = 0.f, y1 = 0.f;
        #pragma unroll
        for (int s = 0; s < 16; s++) {
            float dA = __expf(dtv * Ar[s]);
            h[s] = fmaf(dA, h[s], dtx * Bv[s]);
            if (s & 1) y1 = fmaf(h[s], Cv[s], y1);
            else       y0 = fmaf(h[s], Cv[s], y0);
        }
        float sig = 1.f / (1.f + __expf(-zv));
        yp[(size_t)l*DINNER] = ((y0 + y1) + Dd * xcv) * (zv * sig);

        dtv = ndt; xcv = nxc; zv = nzv;
        B0=nB0; B1=nB1; B2=nB2; B3=nB3;
        C0=nC0; C1=nC1; C2=nC2; C3=nC3;
    }
}

// ---------------- launch ----------------
extern "C" void kernel_launch(void* const* d_in, const int* in_sizes, int n_in,
                              void* d_out, int out_size)
{
    const float* x      = (const float*)d_in[0];
    const float* ln_g   = (const float*)d_in[1];
    const float* ln_b   = (const float*)d_in[2];
    const float* W_in   = (const float*)d_in[3];
    const float* b_in   = (const float*)d_in[4];
    const float* conv_w = (const float*)d_in[5];
    const float* conv_b = (const float*)d_in[6];
    const float* W_x    = (const float*)d_in[7];
    const float* W_dt   = (const float*)d_in[8];
    const float* b_dt   = (const float*)d_in[9];
    const float* A_log  = (const float*)d_in[10];
    const float* Dp     = (const float*)d_in[11];
    const float* W_out  = (const float*)d_in[12];
    const float* b_out  = (const float*)d_in[13];
    float* out = (float*)d_out;

    float *xn, *xzp, *xcp, *xdblp, *partp, *dtp, *yp;
    cudaGetSymbolAddress((void**)&xn,    g_xn);
    cudaGetSymbolAddress((void**)&xzp,   g_xz);
    cudaGetSymbolAddress((void**)&xcp,   g_xc);
    cudaGetSymbolAddress((void**)&xdblp, g_xdbl);
    cudaGetSymbolAddress((void**)&partp, g_part);
    cudaGetSymbolAddress((void**)&dtp,   g_dt);
    cudaGetSymbolAddress((void**)&yp,    g_y);

    // 1. LayerNorm
    ln_kernel<<<ROWS, 256>>>(x, ln_g, ln_b, xn);
    // 2. in projection: xz[2048,4096]
    sgemm_nt<0><<<dim3(2*DINNER/128, ROWS/128), 256>>>(
        xn, DMODEL, W_in, DMODEL, b_in, nullptr, xzp, ROWS, 2*DINNER, DMODEL);
    // 3. depthwise conv + silu
    conv_silu_kernel<<<ROWS*DINNER/256, 256>>>(xzp, conv_w, conv_b, xcp);
    // 4. x_dbl (split-K over 8 chunks + deterministic reduce)
    gemm_xdbl_part<<<dim3(ROWS/32, 8), 256>>>(xcp, W_x, partp);
    xdbl_reduce<<<ROWS*XDBL_W/256, 256>>>(partp, xdblp);
    // 5. dt = softplus(dt_lo @ W_dt^T + b_dt)
    sgemm_nt<1><<<dim3(DINNER/128, ROWS/128), 256>>>(
        xdblp, XDBL_W, W_dt, DTRANK, b_dt, nullptr, dtp, ROWS, DINNER, DTRANK);
    // 6. selective scan + D skip + gate
    scan_kernel<<<dim3(DINNER/32, BATCH), 32>>>(xzp, xcp, xdblp, dtp, A_log, Dp, yp);
    // 7. out projection + residual
    sgemm_nt<2><<<dim3(DMODEL/128, ROWS/128), 256>>>(
        yp, DINNER, W_out, DINNER, b_out, x, out, ROWS, DMODEL, DINNER);
}

// round 2
// speedup vs baseline: 1.6483x; 1.6483x over previous
#include <cuda_runtime.h>
#include <cstddef>
#include <cstdint>

// ---------------- problem constants ----------------
#define BATCH   2
#define SEQ     1024
#define DMODEL  1024
#define DINNER  2048
#define DTRANK  64
#define DSTATE  16
#define DCONV   4
#define ROWS    (BATCH*SEQ)          // 2048
#define XDBL_W  (DTRANK + 2*DSTATE)  // 96

// ---------------- scratch (device globals; no allocs allowed) ----------------
__device__ __align__(16) float g_xn  [ROWS*DMODEL];
__device__ __align__(16) float g_xz  [ROWS*2*DINNER];
__device__ __align__(16) float g_xc  [ROWS*DINNER];
__device__ __align__(16) float g_xdbl[ROWS*XDBL_W];
__device__ __align__(16) float g_part[8*ROWS*XDBL_W];
__device__ __align__(16) float g_dt  [ROWS*DINNER];
__device__ __align__(16) float g_y   [ROWS*DINNER];

// ---------------- LayerNorm ----------------
__global__ __launch_bounds__(256) void ln_kernel(
    const float* __restrict__ x, const float* __restrict__ g,
    const float* __restrict__ b, float* __restrict__ xn)
{
    int row = blockIdx.x;
    int t = threadIdx.x;
    const float4* xr = (const float4*)(x + (size_t)row*DMODEL);
    float4 v = xr[t];
    float s  = v.x + v.y + v.z + v.w;
    float s2 = v.x*v.x + v.y*v.y + v.z*v.z + v.w*v.w;
    #pragma unroll
    for (int o = 16; o; o >>= 1) {
        s  += __shfl_xor_sync(0xffffffffu, s,  o);
        s2 += __shfl_xor_sync(0xffffffffu, s2, o);
    }
    __shared__ float sh[2][8];
    int w = t >> 5;
    if ((t & 31) == 0) { sh[0][w] = s; sh[1][w] = s2; }
    __syncthreads();
    float S = 0.f, S2 = 0.f;
    #pragma unroll
    for (int i = 0; i < 8; i++) { S += sh[0][i]; S2 += sh[1][i]; }
    float mu  = S * (1.f/DMODEL);
    float var = S2 * (1.f/DMODEL) - mu*mu;
    float inv = rsqrtf(var + 1e-5f);
    float4 gv = ((const float4*)g)[t];
    float4 bv = ((const float4*)b)[t];
    float4 o;
    o.x = (v.x - mu)*inv*gv.x + bv.x;
    o.y = (v.y - mu)*inv*gv.y + bv.y;
    o.z = (v.z - mu)*inv*gv.z + bv.z;
    o.w = (v.w - mu)*inv*gv.w + bv.w;
    ((float4*)(xn + (size_t)row*DMODEL))[t] = o;
}

// ---------------- TF32 tensor-core NT GEMM ----------------
// C[M,N] = A[M,K](row, lda) * B[N,K](row, ldb)^T  + bias, epilogue by MODE
// MODE 0: +bias ; MODE 1: softplus(+bias) ; MODE 2: +bias + residual R
__device__ __forceinline__ float softplus_f(float x) {
    return fmaxf(x, 0.f) + log1pf(__expf(-fabsf(x)));
}
__device__ __forceinline__ unsigned f2tf32(float f) {
    unsigned u;
    asm("cvt.rna.tf32.f32 %0, %1;" : "=r"(u) : "f"(f));
    return u;
}
__device__ __forceinline__ void mma_tf32(float c[4], const unsigned a[4], const unsigned b[2]) {
    asm volatile(
      "mma.sync.aligned.m16n8k8.row.col.f32.tf32.tf32.f32 "
      "{%0,%1,%2,%3}, {%4,%5,%6,%7}, {%8,%9}, {%0,%1,%2,%3};"
      : "+f"(c[0]), "+f"(c[1]), "+f"(c[2]), "+f"(c[3])
      : "r"(a[0]), "r"(a[1]), "r"(a[2]), "r"(a[3]), "r"(b[0]), "r"(b[1]));
}

template<int MODE>
__global__ __launch_bounds__(256) void mma_nt(
    const float* __restrict__ A, int lda,
    const float* __restrict__ B, int ldb,
    const float* __restrict__ bias,
    const float* __restrict__ R, int ldr,
    float* __restrict__ C, int ldc,
    int K)
{
    constexpr int BK = 32;
    __shared__ unsigned As[128][BK+4];
    __shared__ unsigned Bs[128][BK+4];
    const int tid  = threadIdx.x;
    const int bm   = blockIdx.y * 128;
    const int bn   = blockIdx.x * 128;
    const int w    = tid >> 5, lane = tid & 31;
    const int wm   = (w & 3) * 32;     // warp row offset in tile
    const int wn   = (w >> 2) * 64;    // warp col offset in tile
    const int g    = lane >> 2;        // 0..7
    const int tg   = lane & 3;         // 0..3

    float acc[2][8][4];
    #pragma unroll
    for (int mi = 0; mi < 2; mi++)
        #pragma unroll
        for (int nj = 0; nj < 8; nj++)
            #pragma unroll
            for (int r = 0; r < 4; r++) acc[mi][nj][r] = 0.f;

    const int lr = tid >> 3;          // 0..31
    const int lc = (tid & 7) * 4;     // 0..28
    const float* Ap = A + (size_t)(bm + lr)*lda + lc;
    const float* Bp = B + (size_t)(bn + lr)*ldb + lc;

    float4 aR[4], bR[4];
    #pragma unroll
    for (int i = 0; i < 4; i++) {
        aR[i] = *(const float4*)(Ap + (size_t)(i*32)*lda);
        bR[i] = *(const float4*)(Bp + (size_t)(i*32)*ldb);
    }

    for (int k0 = 0; k0 < K; k0 += BK) {
        __syncthreads();
        #pragma unroll
        for (int i = 0; i < 4; i++) {
            As[lr + i*32][lc+0] = f2tf32(aR[i].x);
            As[lr + i*32][lc+1] = f2tf32(aR[i].y);
            As[lr + i*32][lc+2] = f2tf32(aR[i].z);
            As[lr + i*32][lc+3] = f2tf32(aR[i].w);
            Bs[lr + i*32][lc+0] = f2tf32(bR[i].x);
            Bs[lr + i*32][lc+1] = f2tf32(bR[i].y);
            Bs[lr + i*32][lc+2] = f2tf32(bR[i].z);
            Bs[lr + i*32][lc+3] = f2tf32(bR[i].w);
        }
        __syncthreads();
        if (k0 + BK < K) {
            Ap += BK; Bp += BK;
            #pragma unroll
            for (int i = 0; i < 4; i++) {
                aR[i] = *(const float4*)(Ap + (size_t)(i*32)*lda);
                bR[i] = *(const float4*)(Bp + (size_t)(i*32)*ldb);
            }
        }
        #pragma unroll
        for (int ks = 0; ks < 4; ks++) {
            const int kk = ks * 8;
            unsigned af[2][4], bf[8][2];
            #pragma unroll
            for (int mi = 0; mi < 2; mi++) {
                int r = wm + mi*16;
                af[mi][0] = As[r + g    ][kk + tg    ];
                af[mi][1] = As[r + g + 8][kk + tg    ];
                af[mi][2] = As[r + g    ][kk + tg + 4];
                af[mi][3] = As[r + g + 8][kk + tg + 4];
            }
            #pragma unroll
            for (int nj = 0; nj < 8; nj++) {
                int c = wn + nj*8 + g;
                bf[nj][0] = Bs[c][kk + tg    ];
                bf[nj][1] = Bs[c][kk + tg + 4];
            }
            #pragma unroll
            for (int mi = 0; mi < 2; mi++)
                #pragma unroll
                for (int nj = 0; nj < 8; nj++)
                    mma_tf32(acc[mi][nj], af[mi], bf[nj]);
        }
    }

    #pragma unroll
    for (int mi = 0; mi < 2; mi++) {
        #pragma unroll
        for (int nj = 0; nj < 8; nj++) {
            int m0 = bm + wm + mi*16 + g;
            int n0 = bn + wn + nj*8 + tg*2;
            float b0v = bias[n0], b1v = bias[n0+1];
            float v00 = acc[mi][nj][0] + b0v;
            float v01 = acc[mi][nj][1] + b1v;
            float v10 = acc[mi][nj][2] + b0v;
            float v11 = acc[mi][nj][3] + b1v;
            if (MODE == 1) {
                v00 = softplus_f(v00); v01 = softplus_f(v01);
                v10 = softplus_f(v10); v11 = softplus_f(v11);
            }
            if (MODE == 2) {
                v00 += R[(size_t)m0*ldr + n0];
                v01 += R[(size_t)m0*ldr + n0 + 1];
                v10 += R[(size_t)(m0+8)*ldr + n0];
                v11 += R[(size_t)(m0+8)*ldr + n0 + 1];
            }
            float2 lo = make_float2(v00, v01);
            float2 hi = make_float2(v10, v11);
            *(float2*)&C[(size_t)m0*ldc + n0]     = lo;
            *(float2*)&C[(size_t)(m0+8)*ldc + n0] = hi;
        }
    }
}

// ---------------- depthwise causal conv (K=4) + SiLU ----------------
__global__ __launch_bounds__(256) void conv_silu_kernel(
    const float* __restrict__ xz, const float* __restrict__ cw,
    const float* __restrict__ cb, float* __restrict__ xc)
{
    int idx = blockIdx.x * 256 + threadIdx.x;
    int d = idx & (DINNER - 1);
    int l = (idx >> 11) & (SEQ - 1);
    const float* base = xz + (size_t)(idx >> 11) * (2*DINNER) + d;
    float4 wv = ((const float4*)cw)[d];
    float x0 = (l >= 3) ? base[-3*2*DINNER] : 0.f;
    float x1 = (l >= 2) ? base[-2*2*DINNER] : 0.f;
    float x2 = (l >= 1) ? base[-1*2*DINNER] : 0.f;
    float x3 = base[0];
    float acc = cb[d];
    acc = fmaf(x0, wv.x, acc);
    acc = fmaf(x1, wv.y, acc);
    acc = fmaf(x2, wv.z, acc);
    acc = fmaf(x3, wv.w, acc);
    float sig = 1.f / (1.f + __expf(-acc));
    xc[idx] = acc * sig;
}

// ---------------- skinny GEMM for x_dbl (split-K) ----------------
__global__ __launch_bounds__(256) void gemm_xdbl_part(
    const float* __restrict__ xc, const float* __restrict__ Wx,
    float* __restrict__ part)
{
    const int KC = DINNER / 8;
    __shared__ float As[32][33];
    __shared__ float Bs[32][97];
    int bm = blockIdx.x * 32;
    int kbase = blockIdx.y * KC;
    int t = threadIdx.x;
    int ty = t >> 5;
    int tx = t & 31;
    float acc[4][3];
    #pragma unroll
    for (int i = 0; i < 4; i++)
        #pragma unroll
        for (int j = 0; j < 3; j++) acc[i][j] = 0.f;

    for (int k0 = 0; k0 < KC; k0 += 32) {
        {
            int m = t >> 3, k4 = (t & 7) * 4;
            float4 v = *(const float4*)(xc + (size_t)(bm + m)*DINNER + kbase + k0 + k4);
            As[k4+0][m]=v.x; As[k4+1][m]=v.y; As[k4+2][m]=v.z; As[k4+3][m]=v.w;
        }
        #pragma unroll
        for (int r = 0; r < 3; r++) {
            int i = t + r*256;
            int e = i >> 3, k4 = (i & 7) * 4;
            float4 v = *(const float4*)(Wx + (size_t)e*DINNER + kbase + k0 + k4);
            Bs[k4+0][e]=v.x; Bs[k4+1][e]=v.y; Bs[k4+2][e]=v.z; Bs[k4+3][e]=v.w;
        }
        __syncthreads();
        #pragma unroll
        for (int kk = 0; kk < 32; kk++) {
            float a0=As[kk][ty*4+0], a1=As[kk][ty*4+1], a2=As[kk][ty*4+2], a3=As[kk][ty*4+3];
            float b0=Bs[kk][tx*3+0], b1=Bs[kk][tx*3+1], b2=Bs[kk][tx*3+2];
            acc[0][0]=fmaf(a0,b0,acc[0][0]); acc[0][1]=fmaf(a0,b1,acc[0][1]); acc[0][2]=fmaf(a0,b2,acc[0][2]);
            acc[1][0]=fmaf(a1,b0,acc[1][0]); acc[1][1]=fmaf(a1,b1,acc[1][1]); acc[1][2]=fmaf(a1,b2,acc[1][2]);
            acc[2][0]=fmaf(a2,b0,acc[2][0]); acc[2][1]=fmaf(a2,b1,acc[2][1]); acc[2][2]=fmaf(a2,b2,acc[2][2]);
            acc[3][0]=fmaf(a3,b0,acc[3][0]); acc[3][1]=fmaf(a3,b1,acc[3][1]); acc[3][2]=fmaf(a3,b2,acc[3][2]);
        }
        __syncthreads();
    }
    #pragma unroll
    for (int i = 0; i < 4; i++)
        #pragma unroll
        for (int j = 0; j < 3; j++)
            part[((size_t)blockIdx.y*ROWS + bm + ty*4 + i)*XDBL_W + tx*3 + j] = acc[i][j];
}

__global__ __launch_bounds__(256) void xdbl_reduce(
    const float* __restrict__ part, float* __restrict__ out)
{
    int i = blockIdx.x * 256 + threadIdx.x;
    float s = 0.f;
    #pragma unroll
    for (int c = 0; c < 8; c++) s += part[(size_t)c*ROWS*XDBL_W + i];
    out[i] = s;
}

// ---------------- selective scan (+D skip, +silu(z) gate) ----------------
__global__ __launch_bounds__(32) void scan_kernel(
    const float* __restrict__ xz, const float* __restrict__ xc,
    const float* __restrict__ xdbl, const float* __restrict__ dt,
    const float* __restrict__ A_log, const float* __restrict__ Dp,
    float* __restrict__ y)
{
    int d = blockIdx.x * 32 + threadIdx.x;
    int b = blockIdx.y;

    float Ar[16], h[16];
    #pragma unroll
    for (int s = 0; s < 16; s++) { Ar[s] = -expf(A_log[(size_t)d*16 + s]); h[s] = 0.f; }
    float Dd = Dp[d];

    const float* dtp = dt   + (size_t)b*SEQ*DINNER + d;
    const float* xcp = xc   + (size_t)b*SEQ*DINNER + d;
    const float* zp  = xz   + (size_t)b*SEQ*(2*DINNER) + DINNER + d;
    const float* bcp = xdbl + (size_t)b*SEQ*XDBL_W + DTRANK;
    float*       yp  = y    + (size_t)b*SEQ*DINNER + d;

    float dtv = dtp[0], xcv = xcp[0], zv = zp[0];
    float4 B0 = *(const float4*)(bcp+0),  B1 = *(const float4*)(bcp+4);
    float4 B2 = *(const float4*)(bcp+8),  B3 = *(const float4*)(bcp+12);
    float4 C0 = *(const float4*)(bcp+16), C1 = *(const float4*)(bcp+20);
    float4 C2 = *(const float4*)(bcp+24), C3 = *(const float4*)(bcp+28);

    for (int l = 0; l < SEQ; l++) {
        int ln = (l + 1 < SEQ) ? l + 1 : l;
        float ndt = dtp[(size_t)ln*DINNER];
        float nxc = xcp[(size_t)ln*DINNER];
        float nzv = zp [(size_t)ln*(2*DINNER)];
        const float* nb = bcp + (size_t)ln*XDBL_W;
        float4 nB0 = *(const float4*)(nb+0),  nB1 = *(const float4*)(nb+4);
        float4 nB2 = *(const float4*)(nb+8),  nB3 = *(const float4*)(nb+12);
        float4 nC0 = *(const float4*)(nb+16), nC1 = *(const float4*)(nb+20);
        float4 nC2 = *(const float4*)(nb+24), nC3 = *(const float4*)(nb+28);

        float Bv[16], Cv[16];
        *(float4*)&Bv[0]=B0; *(float4*)&Bv[4]=B1; *(float4*)&Bv[8]=B2; *(float4*)&Bv[12]=B3;
        *(float4*)&Cv[0]=C0; *(float4*)&Cv[4]=C1; *(float4*)&Cv[8]=C2; *(float4*)&Cv[12]=C3;

        float dtx = dtv * xcv;
        float y0 = 0.f, y1 = 0.f;
        #pragma unroll
        for (int s = 0; s < 16; s++) {
            float dA = __expf(dtv * Ar[s]);
            h[s] = fmaf(dA, h[s], dtx * Bv[s]);
            if (s & 1) y1 = fmaf(h[s], Cv[s], y1);
            else       y0 = fmaf(h[s], Cv[s], y0);
        }
        float sig = 1.f / (1.f + __expf(-zv));
        yp[(size_t)l*DINNER] = ((y0 + y1) + Dd * xcv) * (zv * sig);

        dtv = ndt; xcv = nxc; zv = nzv;
        B0=nB0; B1=nB1; B2=nB2; B3=nB3;
        C0=nC0; C1=nC1; C2=nC2; C3=nC3;
    }
}

// ---------------- launch ----------------
extern "C" void kernel_launch(void* const* d_in, const int* in_sizes, int n_in,
                              void* d_out, int out_size)
{
    const float* x      = (const float*)d_in[0];
    const float* ln_g   = (const float*)d_in[1];
    const float* ln_b   = (const float*)d_in[2];
    const float* W_in   = (const float*)d_in[3];
    const float* b_in   = (const float*)d_in[4];
    const float* conv_w = (const float*)d_in[5];
    const float* conv_b = (const float*)d_in[6];
    const float* W_x    = (const float*)d_in[7];
    const float* W_dt   = (const float*)d_in[8];
    const float* b_dt   = (const float*)d_in[9];
    const float* A_log  = (const float*)d_in[10];
    const float* Dp     = (const float*)d_in[11];
    const float* W_out  = (const float*)d_in[12];
    const float* b_out  = (const float*)d_in[13];
    float* out = (float*)d_out;

    float *xn, *xzp, *xcp, *xdblp, *partp, *dtp, *yp;
    cudaGetSymbolAddress((void**)&xn,    g_xn);
    cudaGetSymbolAddress((void**)&xzp,   g_xz);
    cudaGetSymbolAddress((void**)&xcp,   g_xc);
    cudaGetSymbolAddress((void**)&xdblp, g_xdbl);
    cudaGetSymbolAddress((void**)&partp, g_part);
    cudaGetSymbolAddress((void**)&dtp,   g_dt);
    cudaGetSymbolAddress((void**)&yp,    g_y);

    // 1. LayerNorm
    ln_kernel<<<ROWS, 256>>>(x, ln_g, ln_b, xn);
    // 2. in projection: xz[2048,4096] (TF32 tensor cores)
    mma_nt<0><<<dim3((2*DINNER)/128, ROWS/128), 256>>>(
        xn, DMODEL, W_in, DMODEL, b_in, nullptr, 0, xzp, 2*DINNER, DMODEL);
    // 3. depthwise conv + silu
    conv_silu_kernel<<<ROWS*DINNER/256, 256>>>(xzp, conv_w, conv_b, xcp);
    // 4. x_dbl (split-K + reduce)
    gemm_xdbl_part<<<dim3(ROWS/32, 8), 256>>>(xcp, W_x, partp);
    xdbl_reduce<<<ROWS*XDBL_W/256, 256>>>(partp, xdblp);
    // 5. dt = softplus(dt_lo @ W_dt^T + b_dt) (TF32 tensor cores)
    mma_nt<1><<<dim3(DINNER/128, ROWS/128), 256>>>(
        xdblp, XDBL_W, W_dt, DTRANK, b_dt, nullptr, 0, dtp, DINNER, DTRANK);
    // 6. selective scan + D skip + gate
    scan_kernel<<<dim3(DINNER/32, BATCH), 32>>>(xzp, xcp, xdblp, dtp, A_log, Dp, yp);
    // 7. out projection + residual (TF32 tensor cores)
    mma_nt<2><<<dim3(DMODEL/128, ROWS/128), 256>>>(
        yp, DINNER, W_out, DINNER, b_out, x, DMODEL, out, DMODEL, DINNER);
}

// round 3
// speedup vs baseline: 2.6050x; 1.5804x over previous
#include <cuda_runtime.h>
#include <cstddef>
#include <cstdint>

// ---------------- problem constants ----------------
#define BATCH   2
#define SEQ     1024
#define DMODEL  1024
#define DINNER  2048
#define DTRANK  64
#define DSTATE  16
#define DCONV   4
#define ROWS    (BATCH*SEQ)          // 2048
#define XDBL_W  (DTRANK + 2*DSTATE)  // 96

// ---------------- scratch (device globals; no allocs allowed) ----------------
__device__ __align__(16) float g_xn  [ROWS*DMODEL];
__device__ __align__(16) float g_xz  [ROWS*2*DINNER];
__device__ __align__(16) float g_xc  [ROWS*DINNER];
__device__ __align__(16) float g_xdbl[ROWS*XDBL_W];
__device__ __align__(16) float g_part[8*ROWS*XDBL_W];
__device__ __align__(16) float g_dt  [ROWS*DINNER];
__device__ __align__(16) float g_y   [ROWS*DINNER];
__device__ __align__(16) float g_win [2*DINNER*DMODEL];   // tf32-rounded W_in
__device__ __align__(16) float g_wout[DMODEL*DINNER];     // tf32-rounded W_out

// ---------------- helpers ----------------
__device__ __forceinline__ unsigned f2tf32(float f) {
    unsigned u;
    asm("cvt.rna.tf32.f32 %0, %1;" : "=r"(u) : "f"(f));
    return u;
}
__device__ __forceinline__ float tf32r(float f) { return __uint_as_float(f2tf32(f)); }
__device__ __forceinline__ float softplus_f(float x) {
    return fmaxf(x, 0.f) + log1pf(__expf(-fabsf(x)));
}
__device__ __forceinline__ void mma_tf32(float c[4], const unsigned a[4], const unsigned b[2]) {
    asm volatile(
      "mma.sync.aligned.m16n8k8.row.col.f32.tf32.tf32.f32 "
      "{%0,%1,%2,%3}, {%4,%5,%6,%7}, {%8,%9}, {%0,%1,%2,%3};"
      : "+f"(c[0]), "+f"(c[1]), "+f"(c[2]), "+f"(c[3])
      : "r"(a[0]), "r"(a[1]), "r"(a[2]), "r"(a[3]), "r"(b[0]), "r"(b[1]));
}

// ---------------- tf32 pre-round (for weight matrices) ----------------
__global__ __launch_bounds__(256) void tf32_round_kernel(
    const float* __restrict__ in, float* __restrict__ out)
{
    int i = (blockIdx.x * 256 + threadIdx.x) * 4;
    float4 v = *(const float4*)(in + i);
    v.x = tf32r(v.x); v.y = tf32r(v.y); v.z = tf32r(v.z); v.w = tf32r(v.w);
    *(float4*)(out + i) = v;
}

// ---------------- LayerNorm (emits tf32-rounded xn) ----------------
__global__ __launch_bounds__(256) void ln_kernel(
    const float* __restrict__ x, const float* __restrict__ g,
    const float* __restrict__ b, float* __restrict__ xn)
{
    int row = blockIdx.x;
    int t = threadIdx.x;
    const float4* xr = (const float4*)(x + (size_t)row*DMODEL);
    float4 v = xr[t];
    float s  = v.x + v.y + v.z + v.w;
    float s2 = v.x*v.x + v.y*v.y + v.z*v.z + v.w*v.w;
    #pragma unroll
    for (int o = 16; o; o >>= 1) {
        s  += __shfl_xor_sync(0xffffffffu, s,  o);
        s2 += __shfl_xor_sync(0xffffffffu, s2, o);
    }
    __shared__ float sh[2][8];
    int w = t >> 5;
    if ((t & 31) == 0) { sh[0][w] = s; sh[1][w] = s2; }
    __syncthreads();
    float S = 0.f, S2 = 0.f;
    #pragma unroll
    for (int i = 0; i < 8; i++) { S += sh[0][i]; S2 += sh[1][i]; }
    float mu  = S * (1.f/DMODEL);
    float var = S2 * (1.f/DMODEL) - mu*mu;
    float inv = rsqrtf(var + 1e-5f);
    float4 gv = ((const float4*)g)[t];
    float4 bv = ((const float4*)b)[t];
    float4 o;
    o.x = tf32r((v.x - mu)*inv*gv.x + bv.x);
    o.y = tf32r((v.y - mu)*inv*gv.y + bv.y);
    o.z = tf32r((v.z - mu)*inv*gv.z + bv.z);
    o.w = tf32r((v.w - mu)*inv*gv.w + bv.w);
    ((float4*)(xn + (size_t)row*DMODEL))[t] = o;
}

// ---------------- TF32 tensor-core NT GEMM ----------------
// C[M,N] = A[M,K](row, lda) * B[N,K](row, ldb)^T  + bias, epilogue by MODE
// MODE 0: +bias ; MODE 1: softplus(+bias) ; MODE 2: +bias + residual R
// CVT 1: convert staged values to tf32 ; CVT 0: inputs already tf32-rounded
template<int MODE, int CVT>
__global__ __launch_bounds__(256) void mma_nt(
    const float* __restrict__ A, int lda,
    const float* __restrict__ B, int ldb,
    const float* __restrict__ bias,
    const float* __restrict__ R, int ldr,
    float* __restrict__ C, int ldc,
    int K)
{
    constexpr int BK = 32;
    __shared__ unsigned As[128][BK+4];
    __shared__ unsigned Bs[128][BK+4];
    const int tid  = threadIdx.x;
    const int bm   = blockIdx.y * 128;
    const int bn   = blockIdx.x * 128;
    const int w    = tid >> 5, lane = tid & 31;
    const int wm   = (w & 3) * 32;     // warp row offset in tile
    const int wn   = (w >> 2) * 64;    // warp col offset in tile
    const int g    = lane >> 2;        // 0..7
    const int tg   = lane & 3;         // 0..3

    float acc[2][8][4];
    #pragma unroll
    for (int mi = 0; mi < 2; mi++)
        #pragma unroll
        for (int nj = 0; nj < 8; nj++)
            #pragma unroll
            for (int r = 0; r < 4; r++) acc[mi][nj][r] = 0.f;

    const int lr = tid >> 3;          // 0..31
    const int lc = (tid & 7) * 4;     // 0..28
    const float* Ap = A + (size_t)(bm + lr)*lda + lc;
    const float* Bp = B + (size_t)(bn + lr)*ldb + lc;

    float4 aR[4], bR[4];
    #pragma unroll
    for (int i = 0; i < 4; i++) {
        aR[i] = *(const float4*)(Ap + (size_t)(i*32)*lda);
        bR[i] = *(const float4*)(Bp + (size_t)(i*32)*ldb);
    }

    for (int k0 = 0; k0 < K; k0 += BK) {
        __syncthreads();
        #pragma unroll
        for (int i = 0; i < 4; i++) {
            if (CVT) {
                As[lr + i*32][lc+0] = f2tf32(aR[i].x);
                As[lr + i*32][lc+1] = f2tf32(aR[i].y);
                As[lr + i*32][lc+2] = f2tf32(aR[i].z);
                As[lr + i*32][lc+3] = f2tf32(aR[i].w);
                Bs[lr + i*32][lc+0] = f2tf32(bR[i].x);
                Bs[lr + i*32][lc+1] = f2tf32(bR[i].y);
                Bs[lr + i*32][lc+2] = f2tf32(bR[i].z);
                Bs[lr + i*32][lc+3] = f2tf32(bR[i].w);
            } else {
                As[lr + i*32][lc+0] = __float_as_uint(aR[i].x);
                As[lr + i*32][lc+1] = __float_as_uint(aR[i].y);
                As[lr + i*32][lc+2] = __float_as_uint(aR[i].z);
                As[lr + i*32][lc+3] = __float_as_uint(aR[i].w);
                Bs[lr + i*32][lc+0] = __float_as_uint(bR[i].x);
                Bs[lr + i*32][lc+1] = __float_as_uint(bR[i].y);
                Bs[lr + i*32][lc+2] = __float_as_uint(bR[i].z);
                Bs[lr + i*32][lc+3] = __float_as_uint(bR[i].w);
            }
        }
        __syncthreads();
        if (k0 + BK < K) {
            Ap += BK; Bp += BK;
            #pragma unroll
            for (int i = 0; i < 4; i++) {
                aR[i] = *(const float4*)(Ap + (size_t)(i*32)*lda);
                bR[i] = *(const float4*)(Bp + (size_t)(i*32)*ldb);
            }
        }
        #pragma unroll
        for (int ks = 0; ks < 4; ks++) {
            const int kk = ks * 8;
            unsigned af[2][4], bf[8][2];
            #pragma unroll
            for (int mi = 0; mi < 2; mi++) {
                int r = wm + mi*16;
                af[mi][0] = As[r + g    ][kk + tg    ];
                af[mi][1] = As[r + g + 8][kk + tg    ];
                af[mi][2] = As[r + g    ][kk + tg + 4];
                af[mi][3] = As[r + g + 8][kk + tg + 4];
            }
            #pragma unroll
            for (int nj = 0; nj < 8; nj++) {
                int c = wn + nj*8 + g;
                bf[nj][0] = Bs[c][kk + tg    ];
                bf[nj][1] = Bs[c][kk + tg + 4];
            }
            #pragma unroll
            for (int mi = 0; mi < 2; mi++)
                #pragma unroll
                for (int nj = 0; nj < 8; nj++)
                    mma_tf32(acc[mi][nj], af[mi], bf[nj]);
        }
    }

    #pragma unroll
    for (int mi = 0; mi < 2; mi++) {
        #pragma unroll
        for (int nj = 0; nj < 8; nj++) {
            int m0 = bm + wm + mi*16 + g;
            int n0 = bn + wn + nj*8 + tg*2;
            float b0v = bias[n0], b1v = bias[n0+1];
            float v00 = acc[mi][nj][0] + b0v;
            float v01 = acc[mi][nj][1] + b1v;
            float v10 = acc[mi][nj][2] + b0v;
            float v11 = acc[mi][nj][3] + b1v;
            if (MODE == 1) {
                v00 = softplus_f(v00); v01 = softplus_f(v01);
                v10 = softplus_f(v10); v11 = softplus_f(v11);
            }
            if (MODE == 2) {
                v00 += R[(size_t)m0*ldr + n0];
                v01 += R[(size_t)m0*ldr + n0 + 1];
                v10 += R[(size_t)(m0+8)*ldr + n0];
                v11 += R[(size_t)(m0+8)*ldr + n0 + 1];
            }
            float2 lo = make_float2(v00, v01);
            float2 hi = make_float2(v10, v11);
            *(float2*)&C[(size_t)m0*ldc + n0]     = lo;
            *(float2*)&C[(size_t)(m0+8)*ldc + n0] = hi;
        }
    }
}

// ---------------- depthwise causal conv (K=4) + SiLU ----------------
__global__ __launch_bounds__(256) void conv_silu_kernel(
    const float* __restrict__ xz, const float* __restrict__ cw,
    const float* __restrict__ cb, float* __restrict__ xc)
{
    int idx = blockIdx.x * 256 + threadIdx.x;
    int d = idx & (DINNER - 1);
    int l = (idx >> 11) & (SEQ - 1);
    const float* base = xz + (size_t)(idx >> 11) * (2*DINNER) + d;
    float4 wv = ((const float4*)cw)[d];
    float x0 = (l >= 3) ? base[-3*2*DINNER] : 0.f;
    float x1 = (l >= 2) ? base[-2*2*DINNER] : 0.f;
    float x2 = (l >= 1) ? base[-1*2*DINNER] : 0.f;
    float x3 = base[0];
    float acc = cb[d];
    acc = fmaf(x0, wv.x, acc);
    acc = fmaf(x1, wv.y, acc);
    acc = fmaf(x2, wv.z, acc);
    acc = fmaf(x3, wv.w, acc);
    float sig = 1.f / (1.f + __expf(-acc));
    xc[idx] = acc * sig;
}

// ---------------- skinny GEMM for x_dbl (split-K) ----------------
__global__ __launch_bounds__(256) void gemm_xdbl_part(
    const float* __restrict__ xc, const float* __restrict__ Wx,
    float* __restrict__ part)
{
    const int KC = DINNER / 8;
    __shared__ float As[32][33];
    __shared__ float Bs[32][97];
    int bm = blockIdx.x * 32;
    int kbase = blockIdx.y * KC;
    int t = threadIdx.x;
    int ty = t >> 5;
    int tx = t & 31;
    float acc[4][3];
    #pragma unroll
    for (int i = 0; i < 4; i++)
        #pragma unroll
        for (int j = 0; j < 3; j++) acc[i][j] = 0.f;

    for (int k0 = 0; k0 < KC; k0 += 32) {
        {
            int m = t >> 3, k4 = (t & 7) * 4;
            float4 v = *(const float4*)(xc + (size_t)(bm + m)*DINNER + kbase + k0 + k4);
            As[k4+0][m]=v.x; As[k4+1][m]=v.y; As[k4+2][m]=v.z; As[k4+3][m]=v.w;
        }
        #pragma unroll
        for (int r = 0; r < 3; r++) {
            int i = t + r*256;
            int e = i >> 3, k4 = (i & 7) * 4;
            float4 v = *(const float4*)(Wx + (size_t)e*DINNER + kbase + k0 + k4);
            Bs[k4+0][e]=v.x; Bs[k4+1][e]=v.y; Bs[k4+2][e]=v.z; Bs[k4+3][e]=v.w;
        }
        __syncthreads();
        #pragma unroll
        for (int kk = 0; kk < 32; kk++) {
            float a0=As[kk][ty*4+0], a1=As[kk][ty*4+1], a2=As[kk][ty*4+2], a3=As[kk][ty*4+3];
            float b0=Bs[kk][tx*3+0], b1=Bs[kk][tx*3+1], b2=Bs[kk][tx*3+2];
            acc[0][0]=fmaf(a0,b0,acc[0][0]); acc[0][1]=fmaf(a0,b1,acc[0][1]); acc[0][2]=fmaf(a0,b2,acc[0][2]);
            acc[1][0]=fmaf(a1,b0,acc[1][0]); acc[1][1]=fmaf(a1,b1,acc[1][1]); acc[1][2]=fmaf(a1,b2,acc[1][2]);
            acc[2][0]=fmaf(a2,b0,acc[2][0]); acc[2][1]=fmaf(a2,b1,acc[2][1]); acc[2][2]=fmaf(a2,b2,acc[2][2]);
            acc[3][0]=fmaf(a3,b0,acc[3][0]); acc[3][1]=fmaf(a3,b1,acc[3][1]); acc[3][2]=fmaf(a3,b2,acc[3][2]);
        }
        __syncthreads();
    }
    #pragma unroll
    for (int i = 0; i < 4; i++)
        #pragma unroll
        for (int j = 0; j < 3; j++)
            part[((size_t)blockIdx.y*ROWS + bm + ty*4 + i)*XDBL_W + tx*3 + j] = acc[i][j];
}

__global__ __launch_bounds__(256) void xdbl_reduce(
    const float* __restrict__ part, float* __restrict__ out)
{
    int i = blockIdx.x * 256 + threadIdx.x;
    float s = 0.f;
    #pragma unroll
    for (int c = 0; c < 8; c++) s += part[(size_t)c*ROWS*XDBL_W + i];
    out[i] = s;
}

// ---------------- selective scan v2: 4 lanes/channel, chunk-8 prefetch ----------------
// warp = 8 channels x 4 lanes; lane sub handles states [sub*4, sub*4+4)
// emits tf32-rounded y (y feeds only the out-projection GEMM)
__global__ __launch_bounds__(256) void scan_kernel(
    const float* __restrict__ xz, const float* __restrict__ xc,
    const float* __restrict__ xdbl, const float* __restrict__ dt,
    const float* __restrict__ A_log, const float* __restrict__ Dp,
    float* __restrict__ y)
{
    const int tid  = threadIdx.x;
    const int lane = tid & 31;
    const int warp = tid >> 5;        // 0..7
    const int sub  = lane & 3;        // state quarter
    const int ch   = lane >> 2;       // 0..7
    const int d    = blockIdx.x * 64 + warp * 8 + ch;
    const int b    = blockIdx.y;

    float Ar0 = -expf(A_log[(size_t)d*16 + sub*4 + 0]);
    float Ar1 = -expf(A_log[(size_t)d*16 + sub*4 + 1]);
    float Ar2 = -expf(A_log[(size_t)d*16 + sub*4 + 2]);
    float Ar3 = -expf(A_log[(size_t)d*16 + sub*4 + 3]);
    float h0 = 0.f, h1 = 0.f, h2 = 0.f, h3 = 0.f;
    const float Dd = Dp[d];

    const float* dtp = dt   + (size_t)b*SEQ*DINNER + d;
    const float* xcp = xc   + (size_t)b*SEQ*DINNER + d;
    const float* zp  = xz   + (size_t)b*SEQ*(2*DINNER) + DINNER + d;
    const float* bcp = xdbl + (size_t)b*SEQ*XDBL_W + DTRANK;
    float*       yp  = y    + (size_t)b*SEQ*DINNER + d;

    for (int l0 = 0; l0 < SEQ; l0 += 8) {
        float dtv[8], xcv[8], zv[8];
        float4 Bv[8], Cv[8];
        #pragma unroll
        for (int i = 0; i < 8; i++) {
            int l = l0 + i;
            dtv[i] = dtp[(size_t)l*DINNER];
            xcv[i] = xcp[(size_t)l*DINNER];
            zv[i]  = zp [(size_t)l*(2*DINNER)];
            const float* pb = bcp + (size_t)l*XDBL_W;
            Bv[i] = *(const float4*)(pb + sub*4);
            Cv[i] = *(const float4*)(pb + 16 + sub*4);
        }
        #pragma unroll
        for (int i = 0; i < 8; i++) {
            float dtx = dtv[i] * xcv[i];
            float p0 = __expf(dtv[i] * Ar0);
            float p1 = __expf(dtv[i] * Ar1);
            float p2 = __expf(dtv[i] * Ar2);
            float p3 = __expf(dtv[i] * Ar3);
            h0 = fmaf(p0, h0, dtx * Bv[i].x);
            h1 = fmaf(p1, h1, dtx * Bv[i].y);
            h2 = fmaf(p2, h2, dtx * Bv[i].z);
            h3 = fmaf(p3, h3, dtx * Bv[i].w);
            float yv = h0*Cv[i].x + h1*Cv[i].y + h2*Cv[i].z + h3*Cv[i].w;
            yv += __shfl_xor_sync(0xffffffffu, yv, 1);
            yv += __shfl_xor_sync(0xffffffffu, yv, 2);
            if (sub == 0) {
                float sig = 1.f / (1.f + __expf(-zv[i]));
                float o = (yv + Dd * xcv[i]) * (zv[i] * sig);
                yp[(size_t)(l0 + i)*DINNER] = tf32r(o);
            }
        }
    }
}

// ---------------- launch ----------------
extern "C" void kernel_launch(void* const* d_in, const int* in_sizes, int n_in,
                              void* d_out, int out_size)
{
    const float* x      = (const float*)d_in[0];
    const float* ln_g   = (const float*)d_in[1];
    const float* ln_b   = (const float*)d_in[2];
    const float* W_in   = (const float*)d_in[3];
    const float* b_in   = (const float*)d_in[4];
    const float* conv_w = (const float*)d_in[5];
    const float* conv_b = (const float*)d_in[6];
    const float* W_x    = (const float*)d_in[7];
    const float* W_dt   = (const float*)d_in[8];
    const float* b_dt   = (const float*)d_in[9];
    const float* A_log  = (const float*)d_in[10];
    const float* Dp     = (const float*)d_in[11];
    const float* W_out  = (const float*)d_in[12];
    const float* b_out  = (const float*)d_in[13];
    float* out = (float*)d_out;

    float *xn, *xzp, *xcp, *xdblp, *partp, *dtp, *yp, *winp, *woutp;
    cudaGetSymbolAddress((void**)&xn,    g_xn);
    cudaGetSymbolAddress((void**)&xzp,   g_xz);
    cudaGetSymbolAddress((void**)&xcp,   g_xc);
    cudaGetSymbolAddress((void**)&xdblp, g_xdbl);
    cudaGetSymbolAddress((void**)&partp, g_part);
    cudaGetSymbolAddress((void**)&dtp,   g_dt);
    cudaGetSymbolAddress((void**)&yp,    g_y);
    cudaGetSymbolAddress((void**)&winp,  g_win);
    cudaGetSymbolAddress((void**)&woutp, g_wout);

    // 0. pre-round weights to tf32
    tf32_round_kernel<<<(2*DINNER*DMODEL)/1024, 256>>>(W_in, winp);
    tf32_round_kernel<<<(DMODEL*DINNER)/1024, 256>>>(W_out, woutp);
    // 1. LayerNorm (emits tf32-rounded xn)
    ln_kernel<<<ROWS, 256>>>(x, ln_g, ln_b, xn);
    // 2. in projection: xz[2048,4096] (TF32 tensor cores, pre-rounded inputs)
    mma_nt<0,0><<<dim3((2*DINNER)/128, ROWS/128), 256>>>(
        xn, DMODEL, winp, DMODEL, b_in, nullptr, 0, xzp, 2*DINNER, DMODEL);
    // 3. depthwise conv + silu
    conv_silu_kernel<<<ROWS*DINNER/256, 256>>>(xzp, conv_w, conv_b, xcp);
    // 4. x_dbl (split-K + reduce)
    gemm_xdbl_part<<<dim3(ROWS/32, 8), 256>>>(xcp, W_x, partp);
    xdbl_reduce<<<ROWS*XDBL_W/256, 256>>>(partp, xdblp);
    // 5. dt = softplus(dt_lo @ W_dt^T + b_dt) (TF32, in-loop cvt)
    mma_nt<1,1><<<dim3(DINNER/128, ROWS/128), 256>>>(
        xdblp, XDBL_W, W_dt, DTRANK, b_dt, nullptr, 0, dtp, DINNER, DTRANK);
    // 6. selective scan v2 (emits tf32-rounded y)
    scan_kernel<<<dim3(DINNER/64, BATCH), 256>>>(xzp, xcp, xdblp, dtp, A_log, Dp, yp);
    // 7. out projection + residual (TF32 tensor cores, pre-rounded inputs)
    mma_nt<2,0><<<dim3(DMODEL/128, ROWS/128), 256>>>(
        yp, DINNER, woutp, DINNER, b_out, x, DMODEL, out, DMODEL, DINNER);
}